// round 12
// baseline (speedup 1.0000x reference)
#include <cuda_runtime.h>
#include <math.h>

#define BB 512   // batch
#define TT 256   // time
#define FF 128   // features
#define HH 512   // hidden
#define NCTA 128
#define NT 1024  // threads per CTA (persistent kernel)

// ---------------- scratch (__device__ globals: allocation-free) ----------------
__device__ float g_gamma_h[(size_t)TT * BB * HH];   // [t][b][H]
__device__ float g_gamma_x[(size_t)BB * TT * FF];   // row-major (b*TT+t)
__device__ float g_alpha [(size_t)TT * BB * FF];    // [t][b][F]
__device__ float g_mf    [(size_t)BB * TT * FF];    // float(masks)
__device__ float g_h   [BB * HH];
__device__ float g_hdec[BB * HH];
__device__ float g_xc  [BB * FF];
// Pre-packed gates weights, bf16, m16n8k16 fragment order, 2 k-steps per uint4:
// entry ((ny*16 + c8)*24 + kq32)*32 + lane -> {b0(s), b1(s), b0(s+1), b1(s+1)}, s=2*kq32
__device__ uint4 g_Bpk[16 * 16 * 24 * 32];
__device__ unsigned g_bar;

// ---------------- helpers ----------------
__device__ __forceinline__ unsigned pack_bf16(float lo, float hi) {
    unsigned r;
    asm("cvt.rn.bf16x2.f32 %0, %1, %2;" : "=r"(r) : "f"(hi), "f"(lo));
    return r;
}
__device__ __forceinline__ void mma_bf16(float4& d,
    unsigned a0, unsigned a1, unsigned a2, unsigned a3,
    unsigned b0, unsigned b1)
{
    asm volatile(
        "mma.sync.aligned.m16n8k16.row.col.f32.bf16.bf16.f32 "
        "{%0,%1,%2,%3},{%4,%5,%6,%7},{%8,%9},{%0,%1,%2,%3};"
        : "+f"(d.x), "+f"(d.y), "+f"(d.z), "+f"(d.w)
        : "r"(a0), "r"(a1), "r"(a2), "r"(a3), "r"(b0), "r"(b1));
}
__device__ __forceinline__ float sigf(float x) { return 1.f / (1.f + __expf(-x)); }

__device__ __forceinline__ void gridbar(unsigned& tgt) {
    tgt += NCTA;
    __syncthreads();
    if (threadIdx.x == 0) {
        __threadfence();
        atomicAdd(&g_bar, 1u);
        unsigned v;
        do {
            asm volatile("ld.acquire.gpu.b32 %0, [%1];" : "=r"(v) : "l"(&g_bar) : "memory");
        } while (v < tgt);
    }
    __syncthreads();
}

// ---------------- K1: init + pack ----------------
__global__ void init_pack_kernel(const int* __restrict__ masks,
                                 const float* __restrict__ W_ih,
                                 const float* __restrict__ W_hh)
{
    int bid = blockIdx.x, tid = threadIdx.x;
    int gidx = bid * 256 + tid;
    if (gidx < 16 * 16 * 24 * 32) {   // 196608 uint4 entries
        int idx = gidx;
        int lane = idx & 31;
        int kq32 = (idx >> 5) % 24;
        int c8   = ((idx >> 5) / 24) & 15;
        int ny   = (idx >> 5) / (24 * 16);
        int gID = lane >> 2, tg = lane & 3;
        int c = c8 * 8 + gID;
        int gcol = (c >> 5) * HH + ny * 32 + (c & 31);
        unsigned u[4];
        #pragma unroll
        for (int h = 0; h < 2; h++) {
            int kb = (2 * kq32 + h) * 16;
            #pragma unroll
            for (int p = 0; p < 2; p++) {
                int k0 = kb + 2 * tg + p * 8;
                float w0, w1;
                if (k0 < 256) {
                    w0 = W_ih[(size_t)gcol * 256 + k0];
                    w1 = W_ih[(size_t)gcol * 256 + k0 + 1];
                } else {
                    w0 = W_hh[(size_t)gcol * HH + (k0 - 256)];
                    w1 = W_hh[(size_t)gcol * HH + (k0 - 255)];
                }
                u[h * 2 + p] = pack_bf16(w0, w1);
            }
        }
        g_Bpk[idx] = make_uint4(u[0], u[1], u[2], u[3]);
    }
    int gsz = gridDim.x * 256;
    for (size_t i = gidx; i < (size_t)BB * TT * FF; i += gsz)
        g_mf[i] = (float)masks[i];
    for (int i = gidx; i < BB * HH; i += gsz) g_h[i] = 0.f;
    if (gidx == 0) g_bar = 0u;
}

// ---------------- precompute GEMM body (gamma_h, gamma_x, alpha) ----------------
template<int MODE, int N, int K>
__device__ __forceinline__ void pre_body(float (*As)[65], float (*Ws)[65],
                                         const float* __restrict__ A,
                                         const float* __restrict__ W,
                                         const float* __restrict__ bias, int n0)
{
    const float* baseA  = (MODE == 2) ? (const float*)g_gamma_x : A;
    const float* baseA2 = (MODE == 2) ? (const float*)g_mf      : A;
    int m0 = blockIdx.x * 64;
    int tid = threadIdx.x;
    int ty = tid >> 4, tx = tid & 15;
    float acc[4][4] = {};

    for (int k0 = 0; k0 < K; k0 += 64) {
        #pragma unroll
        for (int v = tid; v < 64 * 64 / 4; v += 256) {
            int r = v >> 4; int kq = (v & 15) * 4;
            int k = k0 + kq;
            const float* src = (k < 128) ? baseA : baseA2;
            int kk = (k < 128) ? k : (k - 128);
            float4 a = *(const float4*)&src[(size_t)(m0 + r) * 128 + kk];
            As[kq + 0][r] = a.x; As[kq + 1][r] = a.y;
            As[kq + 2][r] = a.z; As[kq + 3][r] = a.w;
        }
        #pragma unroll
        for (int v = tid; v < 64 * 64 / 4; v += 256) {
            int r = v >> 4; int kq = (v & 15) * 4;
            float4 w = *(const float4*)&W[(size_t)(n0 + r) * K + k0 + kq];
            Ws[kq + 0][r] = w.x; Ws[kq + 1][r] = w.y;
            Ws[kq + 2][r] = w.z; Ws[kq + 3][r] = w.w;
        }
        __syncthreads();
        #pragma unroll
        for (int kk = 0; kk < 64; kk++) {
            float a[4], w[4];
            #pragma unroll
            for (int i = 0; i < 4; i++) a[i] = As[kk][ty * 4 + i];
            #pragma unroll
            for (int j = 0; j < 4; j++) w[j] = Ws[kk][tx * 4 + j];
            #pragma unroll
            for (int i = 0; i < 4; i++)
                #pragma unroll
                for (int j = 0; j < 4; j++)
                    acc[i][j] += a[i] * w[j];
        }
        __syncthreads();
    }
    #pragma unroll
    for (int i = 0; i < 4; i++) {
        int m = m0 + ty * 4 + i;
        int b = m / TT, t = m % TT;
        #pragma unroll
        for (int j = 0; j < 4; j++) {
            int n = n0 + tx * 4 + j;
            float v = acc[i][j] + bias[n];
            if (MODE == 0)
                g_gamma_h[((size_t)t * BB + b) * HH + n] = expf(-fmaxf(v, 0.f));
            else if (MODE == 1)
                g_gamma_x[(size_t)m * FF + n] = expf(-fmaxf(v, 0.f));
            else
                g_alpha[((size_t)t * BB + b) * FF + n] = v;
        }
    }
}

__global__ void pre01_kernel(const float* __restrict__ deltas,
                             const float* __restrict__ W_dh, const float* __restrict__ b_dh,
                             const float* __restrict__ W_dx, const float* __restrict__ b_dx)
{
    __shared__ float As[64][65];
    __shared__ float Ws[64][65];
    if (blockIdx.y < 8) pre_body<0, HH, FF>(As, Ws, deltas, W_dh, b_dh, blockIdx.y * 64);
    else                pre_body<1, FF, FF>(As, Ws, deltas, W_dx, b_dx, (blockIdx.y - 8) * 64);
}

__global__ void pre2_kernel(const float* __restrict__ W_wc, const float* __restrict__ b_wc)
{
    __shared__ float As[64][65];
    __shared__ float Ws[64][65];
    pre_body<2, FF, 2 * FF>(As, Ws, nullptr, W_wc, b_wc, blockIdx.y * 64);
}

// ---------------- phase-B A-chunk staging (bf16, 1024 threads) ----------------
// Each thread converts 4 floats -> 1 uint2 (4 bf16). As row stride = 36 u32 (32 + pad).
__device__ __forceinline__ void stage_a_chunk(
    unsigned* __restrict__ buf, const float* __restrict__ out_cc,
    int kc, int m0, int t, int tid)
{
    int m = tid >> 4;            // 0..63
    int kq = (tid & 15) * 4;     // float offset within chunk
    int row = m0 + m;
    int k = kc * 64 + kq;
    const float* src;
    size_t ofs;
    if (kc < 2)      { src = out_cc; ofs = ((size_t)row * TT + t) * FF + k; }
    else if (kc < 4) { src = g_mf;   ofs = ((size_t)row * TT + t) * FF + (k - 128); }
    else             { src = g_hdec; ofs = (size_t)row * HH + (k - 256); }
    float4 a = __ldcg((const float4*)&src[ofs]);
    uint2 u = make_uint2(pack_bf16(a.x, a.y), pack_bf16(a.z, a.w));
    *(uint2*)&buf[m * 36 + (kq >> 1)] = u;
}

// ---------------- K4: persistent scan kernel (128 CTAs x 1024 thr) ----------------
// Phase A1: CTA = 8 rows x 64-f half; thread = (f, k-slice of 32), reduce via smem.
//           W_hr slice resident TRANSPOSED [k][f] (conflict-free scalar LDS).
// Phase A2: z_h over K=128, thread = (f, k-slice of 8). W_fr transposed resident.
// Phase B : CTA = 64 rows x 128 gate-cols; 32 warps as 2wm x 16wc; bf16 m16n8k16;
//           B frags from g_Bpk via LDG.128; c-state in registers (2/thread).
__global__ void __launch_bounds__(NT, 1)
loop_kernel(const float* __restrict__ values,
            const float* __restrict__ W_hr, const float* __restrict__ b_hr,
            const float* __restrict__ W_fr, const float* __restrict__ b_fr,
            const float* __restrict__ b_ih, const float* __restrict__ b_hh,
            float* __restrict__ out)
{
    extern __shared__ float sdyn[];
    float* sWhT = sdyn;                          // [512][64] k-major, 32768 fl
    float* sWfT = sdyn + 512 * 64;               // [128][64], 8192 fl
    float* sScr = sdyn + 512 * 64 + 128 * 64;    // scratch: 12288 fl
    unsigned* sAs = (unsigned*)sScr;             // phase B: A double buffer 2 x 64 x 36 u32
    float* sGs  = sScr;                          // phase B epilogue alias [m][c] pad 129
    float* sRed = sScr + 4096;                   // phase A reduction: 16 x 8 x 64

    const int tid = threadIdx.x;
    const int bid = blockIdx.x;

    // phase-A ids
    const int fh  = bid & 1;            // feature half
    const int r0g = (bid >> 1) * 8;     // 8 batch rows
    const int fl  = tid & 63;           // local feature
    const int sl  = tid >> 6;           // k-slice id (0..15)
    const int fg  = fh * 64 + fl;

    // phase-B ids
    const int wid = tid >> 5, lane = tid & 31;
    const int gID = lane >> 2, tg = lane & 3;
    const int wm = wid >> 4, wc = wid & 15;    // 2 x 16
    const int m0 = (bid & 7) * 64;
    const int ny = bid >> 3;
    const int nEp = ny * 32 + lane;

    // resident weight slices, transposed [k][f] (loaded once; one-time conflicts OK)
    for (int it = tid; it < 64 * 128; it += NT) {        // 8192 float4 of W_hr slice
        int ff = it >> 7; int k4 = (it & 127) * 4;
        float4 w = *(const float4*)&W_hr[(size_t)(fh * 64 + ff) * HH + k4];
        sWhT[(k4 + 0) * 64 + ff] = w.x; sWhT[(k4 + 1) * 64 + ff] = w.y;
        sWhT[(k4 + 2) * 64 + ff] = w.z; sWhT[(k4 + 3) * 64 + ff] = w.w;
    }
    for (int it = tid; it < 64 * 32; it += NT) {         // 2048 float4 of W_fr slice
        int ff = it >> 5; int k4 = (it & 31) * 4;
        float4 w = *(const float4*)&W_fr[(size_t)(fh * 64 + ff) * FF + k4];
        sWfT[(k4 + 0) * 64 + ff] = w.x; sWfT[(k4 + 1) * 64 + ff] = w.y;
        sWfT[(k4 + 2) * 64 + ff] = w.z; sWfT[(k4 + 3) * 64 + ff] = w.w;
    }

    // persistent per-thread state
    float c_state[2] = {0.f, 0.f};
    const float bhr = b_hr[fg];
    const float bfr = b_fr[fg];
    const float bi0 = b_ih[0 * HH + nEp] + b_hh[0 * HH + nEp];
    const float bi1 = b_ih[1 * HH + nEp] + b_hh[1 * HH + nEp];
    const float bi2 = b_ih[2 * HH + nEp] + b_hh[2 * HH + nEp];
    const float bi3 = b_ih[3 * HH + nEp] + b_hh[3 * HH + nEp];
    unsigned btgt = 0;
    __syncthreads();

    for (int t = 0; t < TT; t++) {
        // ================= phase A1: h_dec, x_h, x_c =================
        {   // 1024 threads cover 8 rows x 128 float4 exactly
            int i = tid >> 7; int c = (tid & 127) * 4;
            int row = r0g + i;
            float4 hv = __ldcg((const float4*)&g_h[(size_t)row * HH + c]);
            float4 gv = __ldg((const float4*)&g_gamma_h[((size_t)t * BB + row) * HH + c]);
            float4 o = make_float4(hv.x * gv.x, hv.y * gv.y, hv.z * gv.z, hv.w * gv.w);
            *(float4*)&sScr[i * 512 + c] = o;
            if (fh == 0) *(float4*)&g_hdec[(size_t)row * HH + c] = o;
        }
        __syncthreads();

        // thread (fl, sl): partial x_h over k-slice [sl*32, sl*32+32) for all 8 rows
        {
            float accs[8];
            #pragma unroll
            for (int r = 0; r < 8; r++) accs[r] = 0.f;
            const int kb = sl * 32;
            #pragma unroll
            for (int kk = 0; kk < 32; kk += 4) {
                int k = kb + kk;
                float w0 = sWhT[(k + 0) * 64 + fl];
                float w1 = sWhT[(k + 1) * 64 + fl];
                float w2 = sWhT[(k + 2) * 64 + fl];
                float w3 = sWhT[(k + 3) * 64 + fl];
                #pragma unroll
                for (int r = 0; r < 8; r++) {
                    float4 h = *(const float4*)&sScr[r * 512 + k];
                    accs[r] += h.x * w0 + h.y * w1 + h.z * w2 + h.w * w3;
                }
            }
            #pragma unroll
            for (int r = 0; r < 8; r++)
                sRed[sl * 512 + r * 64 + fl] = accs[r];
        }
        __syncthreads();

        float xh = 0.f, m_ = 0.f, x_ = 0.f;
        size_t gofs = 0;
        if (tid < 512) {
            int rO = tid >> 6;
            xh = bhr;
            #pragma unroll
            for (int s = 0; s < 16; s++) xh += sRed[s * 512 + rO * 64 + fl];
            int row = r0g + rO;
            gofs = ((size_t)row * TT + t) * FF + fg;
            m_ = __ldg(&g_mf[gofs]);
            x_ = __ldg(&values[gofs]);
            g_xc[(size_t)row * FF + fg] = m_ * x_ + (1.f - m_) * xh;
        }
        gridbar(btgt);

        // ================= phase A2: z_h, c_h, c_c =================
        {   // 1024 threads cover 8 rows x 128 floats exactly
            int i = tid >> 7; int c = tid & 127;
            sScr[i * 128 + c] = __ldcg(&g_xc[(size_t)(r0g + i) * FF + c]);
        }
        __syncthreads();
        {
            float acz[8];
            #pragma unroll
            for (int r = 0; r < 8; r++) acz[r] = 0.f;
            const int kb = sl * 8;
            #pragma unroll
            for (int kk = 0; kk < 8; kk += 4) {
                int k = kb + kk;
                float w0 = sWfT[(k + 0) * 64 + fl];
                float w1 = sWfT[(k + 1) * 64 + fl];
                float w2 = sWfT[(k + 2) * 64 + fl];
                float w3 = sWfT[(k + 3) * 64 + fl];
                #pragma unroll
                for (int r = 0; r < 8; r++) {
                    float4 xv = *(const float4*)&sScr[r * 128 + k];
                    acz[r] += xv.x * w0 + xv.y * w1 + xv.z * w2 + xv.w * w3;
                }
            }
            #pragma unroll
            for (int r = 0; r < 8; r++)
                sRed[sl * 512 + r * 64 + fl] = acz[r];
        }
        __syncthreads();
        if (tid < 512) {
            int rO = tid >> 6;
            float zh = bfr;
            #pragma unroll
            for (int s = 0; s < 16; s++) zh += sRed[s * 512 + rO * 64 + fl];
            float al = __ldg(&g_alpha[((size_t)t * BB + (r0g + rO)) * FF + fg]);
            float ch = al * zh + (1.f - al) * xh;
            out[gofs] = m_ * x_ + (1.f - m_) * ch;
        }
        gridbar(btgt);

        // ================= phase B: gates GEMM (bf16 mma) + LSTM =================
        float4 acc[2];
        acc[0] = make_float4(0.f, 0.f, 0.f, 0.f);
        acc[1] = make_float4(0.f, 0.f, 0.f, 0.f);

        stage_a_chunk(sAs, out, 0, m0, t, tid);
        __syncthreads();

        #pragma unroll 1
        for (int kc = 0; kc < 12; kc++) {
            const unsigned* As = sAs + (kc & 1) * (64 * 36);

            // B fragments: 2 x LDG.128 per thread (2 k-steps per uint4)
            uint4 bf[2];
            {
                const uint4* bp = &g_Bpk[(((size_t)ny * 16 + wc) * 24 + kc * 2) * 32 + lane];
                bf[0] = __ldg(&bp[0]);
                bf[1] = __ldg(&bp[32]);
            }
            if (kc < 11)
                stage_a_chunk(sAs + ((kc + 1) & 1) * (64 * 36), out, kc + 1, m0, t, tid);

            #pragma unroll
            for (int ks = 0; ks < 4; ks++) {       // 4 k16-steps per 64-k chunk
                int kb = ks * 8;                   // u32-pair offset
                unsigned a[2][4];
                #pragma unroll
                for (int mf = 0; mf < 2; mf++) {
                    int r = wm * 32 + mf * 16 + gID;
                    a[mf][0] = As[(r    ) * 36 + kb + tg];
                    a[mf][1] = As[(r + 8) * 36 + kb + tg];
                    a[mf][2] = As[(r    ) * 36 + kb + tg + 4];
                    a[mf][3] = As[(r + 8) * 36 + kb + tg + 4];
                }
                int q = ks >> 1;
                bool hi = (ks & 1) != 0;
                unsigned b0 = hi ? bf[q].z : bf[q].x;
                unsigned b1 = hi ? bf[q].w : bf[q].y;
                mma_bf16(acc[0], a[0][0], a[0][1], a[0][2], a[0][3], b0, b1);
                mma_bf16(acc[1], a[1][0], a[1][1], a[1][2], a[1][3], b0, b1);
            }
            __syncthreads();
        }

        // exchange gates so each thread sees i,f,g,o for its (m, unit)
        #pragma unroll
        for (int mf = 0; mf < 2; mf++) {
            int rbase = wm * 32 + mf * 16 + gID;
            int cbase = wc * 8 + tg * 2;
            sGs[(rbase    ) * 129 + cbase    ] = acc[mf].x;
            sGs[(rbase    ) * 129 + cbase + 1] = acc[mf].y;
            sGs[(rbase + 8) * 129 + cbase    ] = acc[mf].z;
            sGs[(rbase + 8) * 129 + cbase + 1] = acc[mf].w;
        }
        __syncthreads();

        // fused LSTM pointwise update; c lives in registers
        #pragma unroll
        for (int j = 0; j < 2; j++) {
            int ml = wid + 32 * j;
            float ig  = sigf(sGs[ml * 129 +  0 + lane] + bi0);
            float fgt = sigf(sGs[ml * 129 + 32 + lane] + bi1);
            float gg  = tanhf(sGs[ml * 129 + 64 + lane] + bi2);
            float og  = sigf(sGs[ml * 129 + 96 + lane] + bi3);
            float cn = fgt * c_state[j] + ig * gg;
            c_state[j] = cn;
            g_h[(size_t)(m0 + ml) * HH + nEp] = og * tanhf(cn);
        }
        gridbar(btgt);
    }
}

// ---------------- launch ----------------
extern "C" void kernel_launch(void* const* d_in, const int* in_sizes, int n_in,
                              void* d_out, int out_size)
{
    const float* values = (const float*)d_in[0];
    const int*   masks  = (const int*)  d_in[1];
    const float* deltas = (const float*)d_in[2];
    const float* W_dh = (const float*)d_in[3];
    const float* b_dh = (const float*)d_in[4];
    const float* W_dx = (const float*)d_in[5];
    const float* b_dx = (const float*)d_in[6];
    const float* W_hr = (const float*)d_in[7];
    const float* b_hr = (const float*)d_in[8];
    const float* W_fr = (const float*)d_in[9];
    const float* b_fr = (const float*)d_in[10];
    const float* W_wc = (const float*)d_in[11];
    const float* b_wc = (const float*)d_in[12];
    const float* W_ih = (const float*)d_in[13];
    const float* W_hh = (const float*)d_in[14];
    const float* b_ih = (const float*)d_in[15];
    const float* b_hh = (const float*)d_in[16];
    float* out = (float*)d_out;

    const int SMEM_BYTES = (512 * 64 + 128 * 64 + 12288) * 4;   // 212992
    cudaFuncSetAttribute(loop_kernel, cudaFuncAttributeMaxDynamicSharedMemorySize, SMEM_BYTES);

    init_pack_kernel<<<8192, 256>>>(masks, W_ih, W_hh);                       // launch 1
    pre01_kernel<<<dim3(2048, 10), 256>>>(deltas, W_dh, b_dh, W_dx, b_dx);    // launch 2
    pre2_kernel<<<dim3(2048, 2), 256>>>(W_wc, b_wc);                          // launch 3
    loop_kernel<<<NCTA, NT, SMEM_BYTES>>>(values, W_hr, b_hr, W_fr, b_fr,     // launch 4 (profiled)
                                          b_ih, b_hh, out);
}